// round 15
// baseline (speedup 1.0000x reference)
#include <cuda_runtime.h>
#include <cuda_bf16.h>
#include <cstdint>
#include <stdint.h>
#include <math.h>

#define NN 100000
#define NE 800000
#define DD 96
#define D4 (DD/4)
#define SCAN_B 1024
#define NB_SCAN ((NN + SCAN_B - 1) / SCAN_B)
#define TM 128
#define NT ((NN + TM - 1) / TM)      // 782

#define PADB 208
#define AH_OFF 0
#define AL_OFF (AH_OFF + TM * PADB)
#define WH_OFF (AL_OFF + TM * PADB)
#define WL_OFF (WH_OFF + DD * PADB)
#define SMEM_TOTAL (WL_OFF + DD * PADB)      // 93184

// ---- scratch (static device globals) ----
__device__ __align__(16) float g_h[(size_t)NN * DD];            // h' = (xW)*dinv[row]
__device__ __align__(16) __nv_bfloat16 g_xh[(size_t)NN * DD];
__device__ __align__(16) __nv_bfloat16 g_xl[(size_t)NN * DD];
__device__ __align__(16) __nv_bfloat16 g_w1h[DD * DD], g_w1l[DD * DD];
__device__ __align__(16) __nv_bfloat16 g_w2h[DD * DD], g_w2l[DD * DD];
__device__ int   g_deg[NN];
__device__ float g_dinv[NN];
__device__ int   g_rowptr[NN + 1];
__device__ int   g_cursor[NN];
__device__ int   g_csr_src[NE];
__device__ int   g_blocksums[NB_SCAN];

__device__ __forceinline__ uint32_t smem_u32(const void* p) {
    uint32_t a;
    asm("{ .reg .u64 t; cvta.to.shared.u64 t, %1; cvt.u32.u64 %0, t; }" : "=r"(a) : "l"(p));
    return a;
}
__device__ __forceinline__ void ldsm4(uint32_t* r, uint32_t addr) {
    asm volatile("ldmatrix.sync.aligned.m8n8.x4.shared.b16 {%0,%1,%2,%3}, [%4];"
        : "=r"(r[0]), "=r"(r[1]), "=r"(r[2]), "=r"(r[3]) : "r"(addr));
}
__device__ __forceinline__ void ldsm4t(uint32_t* r, uint32_t addr) {
    asm volatile("ldmatrix.sync.aligned.m8n8.x4.trans.shared.b16 {%0,%1,%2,%3}, [%4];"
        : "=r"(r[0]), "=r"(r[1]), "=r"(r[2]), "=r"(r[3]) : "r"(addr));
}
__device__ __forceinline__ void mma16816(float* c, const uint32_t* a, uint32_t b0, uint32_t b1) {
    asm volatile("mma.sync.aligned.m16n8k16.row.col.f32.bf16.bf16.f32 "
        "{%0,%1,%2,%3}, {%4,%5,%6,%7}, {%8,%9}, {%0,%1,%2,%3};"
        : "+f"(c[0]), "+f"(c[1]), "+f"(c[2]), "+f"(c[3])
        : "r"(a[0]), "r"(a[1]), "r"(a[2]), "r"(a[3]), "r"(b0), "r"(b1));
}

// ---------------- degree / norm / CSR build ----------------
// 4 edges per thread (int4 loads) for MLP on the atomic path
__global__ void count_deg_kernel(const int* __restrict__ dst) {
    int t = blockIdx.x * blockDim.x + threadIdx.x;
    int e = t * 4;
    if (e + 3 < NE) {
        int4 d = __ldg((const int4*)(dst + e));
        if ((unsigned)d.x < NN) atomicAdd(&g_deg[d.x], 1);
        if ((unsigned)d.y < NN) atomicAdd(&g_deg[d.y], 1);
        if ((unsigned)d.z < NN) atomicAdd(&g_deg[d.z], 1);
        if ((unsigned)d.w < NN) atomicAdd(&g_deg[d.w], 1);
    } else {
        for (; e < NE; e++) {
            int d = __ldg(dst + e);
            if ((unsigned)d < NN) atomicAdd(&g_deg[d], 1);
        }
    }
}
__global__ void scan_block_kernel() {   // block scan + dinv (fused)
    __shared__ int sh[SCAN_B];
    int i = blockIdx.x * SCAN_B + threadIdx.x;
    int v = (i < NN) ? g_deg[i] : 0;
    if (i < NN) g_dinv[i] = rsqrtf((float)(v + 1));
    sh[threadIdx.x] = v;
    __syncthreads();
#pragma unroll
    for (int ofs = 1; ofs < SCAN_B; ofs <<= 1) {
        int t = (threadIdx.x >= ofs) ? sh[threadIdx.x - ofs] : 0;
        __syncthreads();
        sh[threadIdx.x] += t;
        __syncthreads();
    }
    if (i < NN) g_rowptr[i] = sh[threadIdx.x] - v;
    if (threadIdx.x == SCAN_B - 1) g_blocksums[blockIdx.x] = sh[SCAN_B - 1];
}
__global__ void scan_add_kernel() {     // per-block reduce of block-sum prefix
    __shared__ int red[128];
    int t = threadIdx.x, bid = blockIdx.x;
    int v = 0;
    if (t < 128) {
        for (int k = t; k < bid; k += 128) v += g_blocksums[k];
        red[t] = v;
    }
    __syncthreads();
#pragma unroll
    for (int o = 64; o > 0; o >>= 1) {
        if (t < o) red[t] += red[t + o];
        __syncthreads();
    }
    int base = red[0];
    int i = bid * SCAN_B + t;
    if (i < NN) {
        int r = g_rowptr[i] + base;
        g_rowptr[i] = r;
        g_cursor[i] = r;
    }
    if (i == 0) g_rowptr[NN] = NE;
}
// 4 edges per thread (int4 loads of src and dst)
__global__ void bin_edges_kernel(const int* __restrict__ ei) {
    int t = blockIdx.x * blockDim.x + threadIdx.x;
    int e = t * 4;
    if (e + 3 < NE) {
        int4 s = __ldg((const int4*)(ei + e));
        int4 d = __ldg((const int4*)(ei + NE + e));
        if ((unsigned)s.x < NN && (unsigned)d.x < NN) g_csr_src[atomicAdd(&g_cursor[d.x], 1)] = s.x;
        if ((unsigned)s.y < NN && (unsigned)d.y < NN) g_csr_src[atomicAdd(&g_cursor[d.y], 1)] = s.y;
        if ((unsigned)s.z < NN && (unsigned)d.z < NN) g_csr_src[atomicAdd(&g_cursor[d.z], 1)] = s.z;
        if ((unsigned)s.w < NN && (unsigned)d.w < NN) g_csr_src[atomicAdd(&g_cursor[d.w], 1)] = s.w;
    } else {
        for (; e < NE; e++) {
            int s = __ldg(ei + e), d = __ldg(ei + NE + e);
            if ((unsigned)s < NN && (unsigned)d < NN)
                g_csr_src[atomicAdd(&g_cursor[d], 1)] = s;
        }
    }
}

// ---------------- weight conversion (both layers, one launch) ----------------
__global__ void convert_w2x(const float* __restrict__ W1, const float* __restrict__ W2) {
    int idx = blockIdx.x * blockDim.x + threadIdx.x;
    if (idx >= 2 * DD * DD) return;
    int which = idx >= DD * DD;
    int i = idx - which * DD * DD;
    float v = which ? W2[i] : W1[i];
    __nv_bfloat16 h = __float2bfloat16(v);
    __nv_bfloat16 l = __float2bfloat16(v - __bfloat162float(h));
    if (which) { g_w2h[i] = h; g_w2l[i] = l; }
    else       { g_w1h[i] = h; g_w1l[i] = l; }
}

// ---------------- mma.sync bf16-split GEMM: out[r,:] = (x @ W) * dinv[r] ----------------
template <int SPLIT>
__global__ void __launch_bounds__(256, 2)
mma_gemm(const float* __restrict__ Xf,
         const __nv_bfloat16* __restrict__ Xh, const __nv_bfloat16* __restrict__ Xl,
         const __nv_bfloat16* __restrict__ Wh, const __nv_bfloat16* __restrict__ Wl,
         float* __restrict__ out) {
    extern __shared__ __align__(16) char smem[];
    const int tid = threadIdx.x, w = tid >> 5, lane = tid & 31;

    {
        int r = tid >> 1, half = tid & 1;
        int gr = blockIdx.x * TM + r;
        if (SPLIT) {
            uint2* dH = (uint2*)(smem + AH_OFF + r * PADB + half * 96);
            uint2* dL = (uint2*)(smem + AL_OFF + r * PADB + half * 96);
            if (gr < NN) {
                const float4* s = (const float4*)(Xf + (size_t)gr * DD) + half * 12;
#pragma unroll
                for (int i = 0; i < 12; i++) {
                    float4 v = s[i];
                    __nv_bfloat162 h0 = __floats2bfloat162_rn(v.x, v.y);
                    __nv_bfloat162 h1 = __floats2bfloat162_rn(v.z, v.w);
                    __nv_bfloat162 l0 = __floats2bfloat162_rn(v.x - __bfloat162float(h0.x),
                                                              v.y - __bfloat162float(h0.y));
                    __nv_bfloat162 l1 = __floats2bfloat162_rn(v.z - __bfloat162float(h1.x),
                                                              v.w - __bfloat162float(h1.y));
                    dH[i] = make_uint2(*(uint32_t*)&h0, *(uint32_t*)&h1);
                    dL[i] = make_uint2(*(uint32_t*)&l0, *(uint32_t*)&l1);
                }
            } else {
                uint2 z = make_uint2(0, 0);
#pragma unroll
                for (int i = 0; i < 12; i++) { dH[i] = z; dL[i] = z; }
            }
        } else {
            uint4* dH = (uint4*)(smem + AH_OFF + r * PADB + half * 96);
            uint4* dL = (uint4*)(smem + AL_OFF + r * PADB + half * 96);
            if (gr < NN) {
                const uint4* sH = (const uint4*)(Xh + (size_t)gr * DD) + half * 6;
                const uint4* sL = (const uint4*)(Xl + (size_t)gr * DD) + half * 6;
#pragma unroll
                for (int i = 0; i < 6; i++) { dH[i] = sH[i]; dL[i] = sL[i]; }
            } else {
                uint4 z = make_uint4(0, 0, 0, 0);
#pragma unroll
                for (int i = 0; i < 6; i++) { dH[i] = z; dL[i] = z; }
            }
        }
    }
    if (tid < DD) {
        uint4* d = (uint4*)(smem + WH_OFF + tid * PADB);
        const uint4* s = (const uint4*)(Wh + (size_t)tid * DD);
#pragma unroll
        for (int i = 0; i < 12; i++) d[i] = s[i];
    } else if (tid >= 128 && tid < 128 + DD) {
        int r = tid - 128;
        uint4* d = (uint4*)(smem + WL_OFF + r * PADB);
        const uint4* s = (const uint4*)(Wl + (size_t)r * DD);
#pragma unroll
        for (int i = 0; i < 12; i++) d[i] = s[i];
    }
    __syncthreads();

    const uint32_t sb = smem_u32(smem);
    float acc[12][4];
#pragma unroll
    for (int t = 0; t < 12; t++)
#pragma unroll
        for (int q = 0; q < 4; q++) acc[t][q] = 0.f;

    const uint32_t aH = sb + AH_OFF + (w * 16 + (lane & 15)) * PADB + (lane >> 4) * 16;
    const uint32_t aL = sb + AL_OFF + (w * 16 + (lane & 15)) * PADB + (lane >> 4) * 16;
    const uint32_t bH = sb + WH_OFF + (lane & 15) * PADB + (lane >> 4) * 16;
    const uint32_t bL = sb + WL_OFF + (lane & 15) * PADB + (lane >> 4) * 16;

#pragma unroll
    for (int ks = 0; ks < 6; ks++) {
        uint32_t ah[4], al[4];
        ldsm4(ah, aH + ks * 32);
        ldsm4(al, aL + ks * 32);
#pragma unroll
        for (int nb = 0; nb < 6; nb++) {
            uint32_t bh[4], bl[4];
            ldsm4t(bh, bH + ks * 16 * PADB + nb * 32);
            ldsm4t(bl, bL + ks * 16 * PADB + nb * 32);
            mma16816(acc[2 * nb],     ah, bh[0], bh[1]);
            mma16816(acc[2 * nb],     ah, bl[0], bl[1]);
            mma16816(acc[2 * nb],     al, bh[0], bh[1]);
            mma16816(acc[2 * nb + 1], ah, bh[2], bh[3]);
            mma16816(acc[2 * nb + 1], ah, bl[2], bl[3]);
            mma16816(acc[2 * nb + 1], al, bh[2], bh[3]);
        }
    }

    int r0 = blockIdx.x * TM + w * 16 + (lane >> 2);
    int c0 = (lane & 3) * 2;
    float d0 = (r0 < NN) ? g_dinv[r0] : 0.f;
    float d1 = (r0 + 8 < NN) ? g_dinv[r0 + 8] : 0.f;
#pragma unroll
    for (int nt = 0; nt < 12; nt++) {
        int col = nt * 8 + c0;
        if (r0 < NN)
            *(float2*)(out + (size_t)r0 * DD + col) = make_float2(acc[nt][0] * d0, acc[nt][1] * d0);
        if (r0 + 8 < NN)
            *(float2*)(out + (size_t)(r0 + 8) * DD + col) = make_float2(acc[nt][2] * d1, acc[nt][3] * d1);
    }
}

// ---------------- pull aggregation (one warp per node, 24 active lanes, 8-edge unroll) ----------------
template <int BN>
__global__ void __launch_bounds__(256)
gather_nodes(const float* __restrict__ h, const float* __restrict__ bias,
             const float* __restrict__ gamma, const float* __restrict__ beta,
             const float* __restrict__ mean,  const float* __restrict__ var,
             float* __restrict__ outf) {
    int n    = (blockIdx.x * blockDim.x + threadIdx.x) >> 5;
    int lane = threadIdx.x & 31;
    if (n >= NN || lane >= D4) return;

    float4 acc = ((const float4*)(h + (size_t)n * DD))[lane];

    int off = g_rowptr[n], end = g_rowptr[n + 1];
    for (; off + 7 < end; off += 8) {
        int s[8];
#pragma unroll
        for (int k = 0; k < 8; k++) s[k] = g_csr_src[off + k];
        float4 v[8];
#pragma unroll
        for (int k = 0; k < 8; k++) v[k] = ((const float4*)(h + (size_t)s[k] * DD))[lane];
#pragma unroll
        for (int k = 0; k < 8; k++) {
            acc.x += v[k].x; acc.y += v[k].y; acc.z += v[k].z; acc.w += v[k].w;
        }
    }
    for (; off + 3 < end; off += 4) {
        int s0 = g_csr_src[off],     s1 = g_csr_src[off + 1];
        int s2 = g_csr_src[off + 2], s3 = g_csr_src[off + 3];
        float4 v0 = ((const float4*)(h + (size_t)s0 * DD))[lane];
        float4 v1 = ((const float4*)(h + (size_t)s1 * DD))[lane];
        float4 v2 = ((const float4*)(h + (size_t)s2 * DD))[lane];
        float4 v3 = ((const float4*)(h + (size_t)s3 * DD))[lane];
        acc.x += v0.x + v1.x + v2.x + v3.x;
        acc.y += v0.y + v1.y + v2.y + v3.y;
        acc.z += v0.z + v1.z + v2.z + v3.z;
        acc.w += v0.w + v1.w + v2.w + v3.w;
    }
    for (; off < end; off++) {
        int s0 = g_csr_src[off];
        float4 v0 = ((const float4*)(h + (size_t)s0 * DD))[lane];
        acc.x += v0.x; acc.y += v0.y; acc.z += v0.z; acc.w += v0.w;
    }

    float dn = g_dinv[n];
    float4 bb = ((const float4*)bias)[lane];
    acc.x = fmaf(acc.x, dn, bb.x);
    acc.y = fmaf(acc.y, dn, bb.y);
    acc.z = fmaf(acc.z, dn, bb.z);
    acc.w = fmaf(acc.w, dn, bb.w);

    if (BN) {
        float4 G = ((const float4*)gamma)[lane];
        float4 B = ((const float4*)beta)[lane];
        float4 M = ((const float4*)mean)[lane];
        float4 V = ((const float4*)var)[lane];
        acc.x = acc.x >= 0.f ? acc.x : 0.05f * acc.x;
        acc.y = acc.y >= 0.f ? acc.y : 0.05f * acc.y;
        acc.z = acc.z >= 0.f ? acc.z : 0.05f * acc.z;
        acc.w = acc.w >= 0.f ? acc.w : 0.05f * acc.w;
        acc.x = fmaf((acc.x - M.x) * rsqrtf(V.x + 1e-5f), G.x, B.x);
        acc.y = fmaf((acc.y - M.y) * rsqrtf(V.y + 1e-5f), G.y, B.y);
        acc.z = fmaf((acc.z - M.z) * rsqrtf(V.z + 1e-5f), G.z, B.z);
        acc.w = fmaf((acc.w - M.w) * rsqrtf(V.w + 1e-5f), G.w, B.w);
        __nv_bfloat162 h0 = __floats2bfloat162_rn(acc.x, acc.y);
        __nv_bfloat162 h1 = __floats2bfloat162_rn(acc.z, acc.w);
        __nv_bfloat162 l0 = __floats2bfloat162_rn(acc.x - __bfloat162float(h0.x), acc.y - __bfloat162float(h0.y));
        __nv_bfloat162 l1 = __floats2bfloat162_rn(acc.z - __bfloat162float(h1.x), acc.w - __bfloat162float(h1.y));
        ((uint2*)g_xh)[n * D4 + lane] = make_uint2(*(uint32_t*)&h0, *(uint32_t*)&h1);
        ((uint2*)g_xl)[n * D4 + lane] = make_uint2(*(uint32_t*)&l0, *(uint32_t*)&l1);
    } else {
        ((float4*)(outf + (size_t)n * DD))[lane] = acc;
    }
}

// ---------------- launcher ----------------
extern "C" void kernel_launch(void* const* d_in, const int* in_sizes, int n_in,
                              void* d_out, int out_size) {
    const float* X     = (const float*)d_in[0];
    const int*   ei    = (const int*)d_in[1];
    const float* W1    = (const float*)d_in[2];
    const float* b1    = (const float*)d_in[3];
    const float* W2    = (const float*)d_in[4];
    const float* b2    = (const float*)d_in[5];
    const float* gamma = (const float*)d_in[6];
    const float* beta  = (const float*)d_in[7];
    const float* mean  = (const float*)d_in[8];
    const float* var   = (const float*)d_in[9];
    float* out = (float*)d_out;

    void* p;
    cudaGetSymbolAddress(&p, g_h);   float* h = (float*)p;
    cudaGetSymbolAddress(&p, g_xh);  __nv_bfloat16* xh = (__nv_bfloat16*)p;
    cudaGetSymbolAddress(&p, g_xl);  __nv_bfloat16* xl = (__nv_bfloat16*)p;
    cudaGetSymbolAddress(&p, g_w1h); __nv_bfloat16* w1h = (__nv_bfloat16*)p;
    cudaGetSymbolAddress(&p, g_w1l); __nv_bfloat16* w1l = (__nv_bfloat16*)p;
    cudaGetSymbolAddress(&p, g_w2h); __nv_bfloat16* w2h = (__nv_bfloat16*)p;
    cudaGetSymbolAddress(&p, g_w2l); __nv_bfloat16* w2l = (__nv_bfloat16*)p;
    void* degp; cudaGetSymbolAddress(&degp, g_deg);

    cudaFuncSetAttribute(mma_gemm<0>, cudaFuncAttributeMaxDynamicSharedMemorySize, SMEM_TOTAL);
    cudaFuncSetAttribute(mma_gemm<1>, cudaFuncAttributeMaxDynamicSharedMemorySize, SMEM_TOTAL);

    static cudaStream_t s2 = nullptr;
    static cudaEvent_t evA = nullptr, evD = nullptr, evG = nullptr;
    if (!s2) {
        cudaStreamCreate(&s2);
        cudaEventCreateWithFlags(&evA, cudaEventDisableTiming);
        cudaEventCreateWithFlags(&evD, cudaEventDisableTiming);
        cudaEventCreateWithFlags(&evG, cudaEventDisableTiming);
    }

    const int TPB = 256;
    int edge4Blocks = (NE / 4 + TPB - 1) / TPB;
    int wBlocks     = (2 * DD * DD + TPB - 1) / TPB;
    int gathBlocks  = (NN + 7) / 8;

    // ---- stream 0: degree -> scan(+dinv) -> add -> bin ----
    cudaEventRecord(evA, 0);
    cudaMemsetAsync(degp, 0, NN * sizeof(int), 0);
    count_deg_kernel<<<edge4Blocks, TPB>>>(ei + NE);
    scan_block_kernel<<<NB_SCAN, SCAN_B>>>();      // also writes dinv
    cudaEventRecord(evD, 0);
    scan_add_kernel<<<NB_SCAN, SCAN_B>>>();
    bin_edges_kernel<<<edge4Blocks, TPB>>>(ei);

    // ---- stream s2: weight conversion + layer-1 GEMM (overlaps scan/bin) ----
    cudaStreamWaitEvent(s2, evA, 0);
    convert_w2x<<<wBlocks, TPB, 0, s2>>>(W1, W2);
    cudaStreamWaitEvent(s2, evD, 0);
    mma_gemm<1><<<NT, 256, SMEM_TOTAL, s2>>>(X, nullptr, nullptr, w1h, w1l, h);
    cudaEventRecord(evG, s2);

    // ---- join: gather1 needs CSR (stream 0) + h' (s2) ----
    cudaStreamWaitEvent(0, evG, 0);
    gather_nodes<1><<<gathBlocks, TPB>>>(h, b1, gamma, beta, mean, var, nullptr);

    // layer 2 (serial)
    mma_gemm<0><<<NT, 256, SMEM_TOTAL>>>(nullptr, xh, xl, w2h, w2l, h);
    gather_nodes<0><<<gathBlocks, TPB>>>(h, b2, gamma, beta, mean, var, out);
}

// round 16
// speedup vs baseline: 1.0409x; 1.0409x over previous
#include <cuda_runtime.h>
#include <cuda_bf16.h>
#include <cstdint>
#include <stdint.h>
#include <math.h>

#define NN 100000
#define NE 800000
#define DD 96
#define D4 (DD/4)
#define SCAN_B 1024
#define NB_SCAN ((NN + SCAN_B - 1) / SCAN_B)
#define TM 128
#define NT ((NN + TM - 1) / TM)      // 782

#define PADB 208
#define AH_OFF 0
#define AL_OFF (AH_OFF + TM * PADB)
#define WH_OFF (AL_OFF + TM * PADB)
#define WL_OFF (WH_OFF + DD * PADB)
#define SMEM_TOTAL (WL_OFF + DD * PADB)      // 93184

// ---- scratch (static device globals) ----
__device__ __align__(16) float g_h[(size_t)NN * DD];            // h' = (xW)*dinv[row]
__device__ __align__(16) __nv_bfloat16 g_xh[(size_t)NN * DD];
__device__ __align__(16) __nv_bfloat16 g_xl[(size_t)NN * DD];
__device__ __align__(16) __nv_bfloat16 g_w1h[DD * DD], g_w1l[DD * DD];
__device__ __align__(16) __nv_bfloat16 g_w2h[DD * DD], g_w2l[DD * DD];
__device__ int   g_deg[NN];
__device__ float g_dinv[NN];
__device__ int   g_rowptr[NN + 1];
__device__ int   g_cursor[NN];
__device__ int   g_csr_src[NE];
__device__ int   g_blocksums[NB_SCAN];

__device__ __forceinline__ uint32_t smem_u32(const void* p) {
    uint32_t a;
    asm("{ .reg .u64 t; cvta.to.shared.u64 t, %1; cvt.u32.u64 %0, t; }" : "=r"(a) : "l"(p));
    return a;
}
__device__ __forceinline__ void ldsm4(uint32_t* r, uint32_t addr) {
    asm volatile("ldmatrix.sync.aligned.m8n8.x4.shared.b16 {%0,%1,%2,%3}, [%4];"
        : "=r"(r[0]), "=r"(r[1]), "=r"(r[2]), "=r"(r[3]) : "r"(addr));
}
__device__ __forceinline__ void ldsm4t(uint32_t* r, uint32_t addr) {
    asm volatile("ldmatrix.sync.aligned.m8n8.x4.trans.shared.b16 {%0,%1,%2,%3}, [%4];"
        : "=r"(r[0]), "=r"(r[1]), "=r"(r[2]), "=r"(r[3]) : "r"(addr));
}
__device__ __forceinline__ void mma16816(float* c, const uint32_t* a, uint32_t b0, uint32_t b1) {
    asm volatile("mma.sync.aligned.m16n8k16.row.col.f32.bf16.bf16.f32 "
        "{%0,%1,%2,%3}, {%4,%5,%6,%7}, {%8,%9}, {%0,%1,%2,%3};"
        : "+f"(c[0]), "+f"(c[1]), "+f"(c[2]), "+f"(c[3])
        : "r"(a[0]), "r"(a[1]), "r"(a[2]), "r"(a[3]), "r"(b0), "r"(b1));
}

// ---------------- degree / norm / CSR build ----------------
__global__ void count_deg_kernel(const int* __restrict__ dst) {
    int e = blockIdx.x * blockDim.x + threadIdx.x;
    if (e < NE) { int d = __ldg(dst + e); if ((unsigned)d < NN) atomicAdd(&g_deg[d], 1); }
}
// block scan (shfl-based) + dinv (fused)
__global__ void scan_block_kernel() {
    __shared__ int wsum[32];
    int i = blockIdx.x * SCAN_B + threadIdx.x;
    int lane = threadIdx.x & 31, wid = threadIdx.x >> 5;
    int v = (i < NN) ? g_deg[i] : 0;
    if (i < NN) g_dinv[i] = rsqrtf((float)(v + 1));
    int x = v;
#pragma unroll
    for (int o = 1; o < 32; o <<= 1) {
        int t = __shfl_up_sync(0xFFFFFFFFu, x, o);
        if (lane >= o) x += t;
    }
    if (lane == 31) wsum[wid] = x;
    __syncthreads();
    if (wid == 0) {
        int s = wsum[lane];
        int y = s;
#pragma unroll
        for (int o = 1; o < 32; o <<= 1) {
            int t = __shfl_up_sync(0xFFFFFFFFu, y, o);
            if (lane >= o) y += t;
        }
        wsum[lane] = y - s;   // exclusive warp prefix
    }
    __syncthreads();
    int incl = x + wsum[wid];
    if (i < NN) g_rowptr[i] = incl - v;   // exclusive
    if (threadIdx.x == SCAN_B - 1) g_blocksums[blockIdx.x] = incl;
}
__global__ void scan_add_kernel() {     // per-block reduce of block-sum prefix
    __shared__ int red[128];
    int t = threadIdx.x, bid = blockIdx.x;
    int v = 0;
    if (t < 128) {
        for (int k = t; k < bid; k += 128) v += g_blocksums[k];
        red[t] = v;
    }
    __syncthreads();
#pragma unroll
    for (int o = 64; o > 0; o >>= 1) {
        if (t < o) red[t] += red[t + o];
        __syncthreads();
    }
    int base = red[0];
    int i = bid * SCAN_B + t;
    if (i < NN) {
        int r = g_rowptr[i] + base;
        g_rowptr[i] = r;
        g_cursor[i] = r;
    }
    if (i == 0) g_rowptr[NN] = NE;
}
__global__ void bin_edges_kernel(const int* __restrict__ ei) {
    int e = blockIdx.x * blockDim.x + threadIdx.x;
    if (e >= NE) return;
    int s = __ldg(ei + e), d = __ldg(ei + NE + e);
    if ((unsigned)s >= NN || (unsigned)d >= NN) return;
    g_csr_src[atomicAdd(&g_cursor[d], 1)] = s;
}

// ---------------- weight conversion (both layers, one launch) ----------------
__global__ void convert_w2x(const float* __restrict__ W1, const float* __restrict__ W2) {
    int idx = blockIdx.x * blockDim.x + threadIdx.x;
    if (idx >= 2 * DD * DD) return;
    int which = idx >= DD * DD;
    int i = idx - which * DD * DD;
    float v = which ? W2[i] : W1[i];
    __nv_bfloat16 h = __float2bfloat16(v);
    __nv_bfloat16 l = __float2bfloat16(v - __bfloat162float(h));
    if (which) { g_w2h[i] = h; g_w2l[i] = l; }
    else       { g_w1h[i] = h; g_w1l[i] = l; }
}

// ---------------- mma.sync bf16-split GEMM: out[r,:] = (x @ W) * dinv[r] ----------------
template <int SPLIT>
__global__ void __launch_bounds__(256, 2)
mma_gemm(const float* __restrict__ Xf,
         const __nv_bfloat16* __restrict__ Xh, const __nv_bfloat16* __restrict__ Xl,
         const __nv_bfloat16* __restrict__ Wh, const __nv_bfloat16* __restrict__ Wl,
         float* __restrict__ out) {
    extern __shared__ __align__(16) char smem[];
    const int tid = threadIdx.x, w = tid >> 5, lane = tid & 31;

    {
        int r = tid >> 1, half = tid & 1;
        int gr = blockIdx.x * TM + r;
        if (SPLIT) {
            uint2* dH = (uint2*)(smem + AH_OFF + r * PADB + half * 96);
            uint2* dL = (uint2*)(smem + AL_OFF + r * PADB + half * 96);
            if (gr < NN) {
                const float4* s = (const float4*)(Xf + (size_t)gr * DD) + half * 12;
#pragma unroll
                for (int i = 0; i < 12; i++) {
                    float4 v = s[i];
                    __nv_bfloat162 h0 = __floats2bfloat162_rn(v.x, v.y);
                    __nv_bfloat162 h1 = __floats2bfloat162_rn(v.z, v.w);
                    __nv_bfloat162 l0 = __floats2bfloat162_rn(v.x - __bfloat162float(h0.x),
                                                              v.y - __bfloat162float(h0.y));
                    __nv_bfloat162 l1 = __floats2bfloat162_rn(v.z - __bfloat162float(h1.x),
                                                              v.w - __bfloat162float(h1.y));
                    dH[i] = make_uint2(*(uint32_t*)&h0, *(uint32_t*)&h1);
                    dL[i] = make_uint2(*(uint32_t*)&l0, *(uint32_t*)&l1);
                }
            } else {
                uint2 z = make_uint2(0, 0);
#pragma unroll
                for (int i = 0; i < 12; i++) { dH[i] = z; dL[i] = z; }
            }
        } else {
            uint4* dH = (uint4*)(smem + AH_OFF + r * PADB + half * 96);
            uint4* dL = (uint4*)(smem + AL_OFF + r * PADB + half * 96);
            if (gr < NN) {
                const uint4* sH = (const uint4*)(Xh + (size_t)gr * DD) + half * 6;
                const uint4* sL = (const uint4*)(Xl + (size_t)gr * DD) + half * 6;
#pragma unroll
                for (int i = 0; i < 6; i++) { dH[i] = sH[i]; dL[i] = sL[i]; }
            } else {
                uint4 z = make_uint4(0, 0, 0, 0);
#pragma unroll
                for (int i = 0; i < 6; i++) { dH[i] = z; dL[i] = z; }
            }
        }
    }
    if (tid < DD) {
        uint4* d = (uint4*)(smem + WH_OFF + tid * PADB);
        const uint4* s = (const uint4*)(Wh + (size_t)tid * DD);
#pragma unroll
        for (int i = 0; i < 12; i++) d[i] = s[i];
    } else if (tid >= 128 && tid < 128 + DD) {
        int r = tid - 128;
        uint4* d = (uint4*)(smem + WL_OFF + r * PADB);
        const uint4* s = (const uint4*)(Wl + (size_t)r * DD);
#pragma unroll
        for (int i = 0; i < 12; i++) d[i] = s[i];
    }
    __syncthreads();

    const uint32_t sb = smem_u32(smem);
    float acc[12][4];
#pragma unroll
    for (int t = 0; t < 12; t++)
#pragma unroll
        for (int q = 0; q < 4; q++) acc[t][q] = 0.f;

    const uint32_t aH = sb + AH_OFF + (w * 16 + (lane & 15)) * PADB + (lane >> 4) * 16;
    const uint32_t aL = sb + AL_OFF + (w * 16 + (lane & 15)) * PADB + (lane >> 4) * 16;
    const uint32_t bH = sb + WH_OFF + (lane & 15) * PADB + (lane >> 4) * 16;
    const uint32_t bL = sb + WL_OFF + (lane & 15) * PADB + (lane >> 4) * 16;

#pragma unroll
    for (int ks = 0; ks < 6; ks++) {
        uint32_t ah[4], al[4];
        ldsm4(ah, aH + ks * 32);
        ldsm4(al, aL + ks * 32);
#pragma unroll
        for (int nb = 0; nb < 6; nb++) {
            uint32_t bh[4], bl[4];
            ldsm4t(bh, bH + ks * 16 * PADB + nb * 32);
            ldsm4t(bl, bL + ks * 16 * PADB + nb * 32);
            mma16816(acc[2 * nb],     ah, bh[0], bh[1]);
            mma16816(acc[2 * nb],     ah, bl[0], bl[1]);
            mma16816(acc[2 * nb],     al, bh[0], bh[1]);
            mma16816(acc[2 * nb + 1], ah, bh[2], bh[3]);
            mma16816(acc[2 * nb + 1], ah, bl[2], bl[3]);
            mma16816(acc[2 * nb + 1], al, bh[2], bh[3]);
        }
    }

    int r0 = blockIdx.x * TM + w * 16 + (lane >> 2);
    int c0 = (lane & 3) * 2;
    float d0 = (r0 < NN) ? g_dinv[r0] : 0.f;
    float d1 = (r0 + 8 < NN) ? g_dinv[r0 + 8] : 0.f;
#pragma unroll
    for (int nt = 0; nt < 12; nt++) {
        int col = nt * 8 + c0;
        if (r0 < NN)
            *(float2*)(out + (size_t)r0 * DD + col) = make_float2(acc[nt][0] * d0, acc[nt][1] * d0);
        if (r0 + 8 < NN)
            *(float2*)(out + (size_t)(r0 + 8) * DD + col) = make_float2(acc[nt][2] * d1, acc[nt][3] * d1);
    }
}

// ---------------- pull aggregation (one warp per node, 24 active lanes, 8-edge unroll) ----------------
template <int BN>
__global__ void __launch_bounds__(256)
gather_nodes(const float* __restrict__ h, const float* __restrict__ bias,
             const float* __restrict__ gamma, const float* __restrict__ beta,
             const float* __restrict__ mean,  const float* __restrict__ var,
             float* __restrict__ outf) {
    int n    = (blockIdx.x * blockDim.x + threadIdx.x) >> 5;
    int lane = threadIdx.x & 31;
    if (n >= NN || lane >= D4) return;

    float4 acc = ((const float4*)(h + (size_t)n * DD))[lane];

    int off = g_rowptr[n], end = g_rowptr[n + 1];
    for (; off + 7 < end; off += 8) {
        int s[8];
#pragma unroll
        for (int k = 0; k < 8; k++) s[k] = g_csr_src[off + k];
        float4 v[8];
#pragma unroll
        for (int k = 0; k < 8; k++) v[k] = ((const float4*)(h + (size_t)s[k] * DD))[lane];
#pragma unroll
        for (int k = 0; k < 8; k++) {
            acc.x += v[k].x; acc.y += v[k].y; acc.z += v[k].z; acc.w += v[k].w;
        }
    }
    for (; off + 3 < end; off += 4) {
        int s0 = g_csr_src[off],     s1 = g_csr_src[off + 1];
        int s2 = g_csr_src[off + 2], s3 = g_csr_src[off + 3];
        float4 v0 = ((const float4*)(h + (size_t)s0 * DD))[lane];
        float4 v1 = ((const float4*)(h + (size_t)s1 * DD))[lane];
        float4 v2 = ((const float4*)(h + (size_t)s2 * DD))[lane];
        float4 v3 = ((const float4*)(h + (size_t)s3 * DD))[lane];
        acc.x += v0.x + v1.x + v2.x + v3.x;
        acc.y += v0.y + v1.y + v2.y + v3.y;
        acc.z += v0.z + v1.z + v2.z + v3.z;
        acc.w += v0.w + v1.w + v2.w + v3.w;
    }
    for (; off < end; off++) {
        int s0 = g_csr_src[off];
        float4 v0 = ((const float4*)(h + (size_t)s0 * DD))[lane];
        acc.x += v0.x; acc.y += v0.y; acc.z += v0.z; acc.w += v0.w;
    }

    float dn = g_dinv[n];
    float4 bb = ((const float4*)bias)[lane];
    acc.x = fmaf(acc.x, dn, bb.x);
    acc.y = fmaf(acc.y, dn, bb.y);
    acc.z = fmaf(acc.z, dn, bb.z);
    acc.w = fmaf(acc.w, dn, bb.w);

    if (BN) {
        float4 G = ((const float4*)gamma)[lane];
        float4 B = ((const float4*)beta)[lane];
        float4 M = ((const float4*)mean)[lane];
        float4 V = ((const float4*)var)[lane];
        acc.x = acc.x >= 0.f ? acc.x : 0.05f * acc.x;
        acc.y = acc.y >= 0.f ? acc.y : 0.05f * acc.y;
        acc.z = acc.z >= 0.f ? acc.z : 0.05f * acc.z;
        acc.w = acc.w >= 0.f ? acc.w : 0.05f * acc.w;
        acc.x = fmaf((acc.x - M.x) * rsqrtf(V.x + 1e-5f), G.x, B.x);
        acc.y = fmaf((acc.y - M.y) * rsqrtf(V.y + 1e-5f), G.y, B.y);
        acc.z = fmaf((acc.z - M.z) * rsqrtf(V.z + 1e-5f), G.z, B.z);
        acc.w = fmaf((acc.w - M.w) * rsqrtf(V.w + 1e-5f), G.w, B.w);
        __nv_bfloat162 h0 = __floats2bfloat162_rn(acc.x, acc.y);
        __nv_bfloat162 h1 = __floats2bfloat162_rn(acc.z, acc.w);
        __nv_bfloat162 l0 = __floats2bfloat162_rn(acc.x - __bfloat162float(h0.x), acc.y - __bfloat162float(h0.y));
        __nv_bfloat162 l1 = __floats2bfloat162_rn(acc.z - __bfloat162float(h1.x), acc.w - __bfloat162float(h1.y));
        ((uint2*)g_xh)[n * D4 + lane] = make_uint2(*(uint32_t*)&h0, *(uint32_t*)&h1);
        ((uint2*)g_xl)[n * D4 + lane] = make_uint2(*(uint32_t*)&l0, *(uint32_t*)&l1);
    } else {
        ((float4*)(outf + (size_t)n * DD))[lane] = acc;
    }
}

// ---------------- launcher ----------------
extern "C" void kernel_launch(void* const* d_in, const int* in_sizes, int n_in,
                              void* d_out, int out_size) {
    const float* X     = (const float*)d_in[0];
    const int*   ei    = (const int*)d_in[1];
    const float* W1    = (const float*)d_in[2];
    const float* b1    = (const float*)d_in[3];
    const float* W2    = (const float*)d_in[4];
    const float* b2    = (const float*)d_in[5];
    const float* gamma = (const float*)d_in[6];
    const float* beta  = (const float*)d_in[7];
    const float* mean  = (const float*)d_in[8];
    const float* var   = (const float*)d_in[9];
    float* out = (float*)d_out;

    void* p;
    cudaGetSymbolAddress(&p, g_h);   float* h = (float*)p;
    cudaGetSymbolAddress(&p, g_xh);  __nv_bfloat16* xh = (__nv_bfloat16*)p;
    cudaGetSymbolAddress(&p, g_xl);  __nv_bfloat16* xl = (__nv_bfloat16*)p;
    cudaGetSymbolAddress(&p, g_w1h); __nv_bfloat16* w1h = (__nv_bfloat16*)p;
    cudaGetSymbolAddress(&p, g_w1l); __nv_bfloat16* w1l = (__nv_bfloat16*)p;
    cudaGetSymbolAddress(&p, g_w2h); __nv_bfloat16* w2h = (__nv_bfloat16*)p;
    cudaGetSymbolAddress(&p, g_w2l); __nv_bfloat16* w2l = (__nv_bfloat16*)p;
    void* degp; cudaGetSymbolAddress(&degp, g_deg);

    cudaFuncSetAttribute(mma_gemm<0>, cudaFuncAttributeMaxDynamicSharedMemorySize, SMEM_TOTAL);
    cudaFuncSetAttribute(mma_gemm<1>, cudaFuncAttributeMaxDynamicSharedMemorySize, SMEM_TOTAL);

    static cudaStream_t s2 = nullptr;
    static cudaEvent_t evA = nullptr, evD = nullptr, evG = nullptr;
    if (!s2) {
        cudaStreamCreate(&s2);
        cudaEventCreateWithFlags(&evA, cudaEventDisableTiming);
        cudaEventCreateWithFlags(&evD, cudaEventDisableTiming);
        cudaEventCreateWithFlags(&evG, cudaEventDisableTiming);
    }

    const int TPB = 256;
    int edgeBlocks = (NE + TPB - 1) / TPB;
    int wBlocks    = (2 * DD * DD + TPB - 1) / TPB;
    int gathBlocks = (NN + 7) / 8;

    // ---- stream 0: degree -> scan(+dinv) -> add -> bin ----
    cudaEventRecord(evA, 0);
    cudaMemsetAsync(degp, 0, NN * sizeof(int), 0);
    count_deg_kernel<<<edgeBlocks, TPB>>>(ei + NE);
    scan_block_kernel<<<NB_SCAN, SCAN_B>>>();      // also writes dinv
    cudaEventRecord(evD, 0);
    scan_add_kernel<<<NB_SCAN, SCAN_B>>>();
    bin_edges_kernel<<<edgeBlocks, TPB>>>(ei);

    // ---- stream s2: weight conversion + layer-1 GEMM (overlaps scan/bin) ----
    cudaStreamWaitEvent(s2, evA, 0);
    convert_w2x<<<wBlocks, TPB, 0, s2>>>(W1, W2);
    cudaStreamWaitEvent(s2, evD, 0);
    mma_gemm<1><<<NT, 256, SMEM_TOTAL, s2>>>(X, nullptr, nullptr, w1h, w1l, h);
    cudaEventRecord(evG, s2);

    // ---- join: gather1 needs CSR (stream 0) + h' (s2) ----
    cudaStreamWaitEvent(0, evG, 0);
    gather_nodes<1><<<gathBlocks, TPB>>>(h, b1, gamma, beta, mean, var, nullptr);

    // layer 2 (serial)
    mma_gemm<0><<<NT, 256, SMEM_TOTAL>>>(nullptr, xh, xl, w2h, w2l, h);
    gather_nodes<0><<<gathBlocks, TPB>>>(h, b2, gamma, beta, mean, var, out);
}

// round 17
// speedup vs baseline: 1.0817x; 1.0392x over previous
#include <cuda_runtime.h>
#include <cuda_bf16.h>
#include <cuda_fp16.h>
#include <cstdint>
#include <stdint.h>
#include <math.h>

#define NN 100000
#define NE 800000
#define DD 96
#define D4 (DD/4)
#define SCAN_B 1024
#define NB_SCAN ((NN + SCAN_B - 1) / SCAN_B)
#define TM 128
#define NT ((NN + TM - 1) / TM)      // 782

#define PADB 208
#define AH_OFF 0
#define AL_OFF (AH_OFF + TM * PADB)
#define WH_OFF (AL_OFF + TM * PADB)
#define WL_OFF (WH_OFF + DD * PADB)
#define SMEM_TOTAL (WL_OFF + DD * PADB)      // 93184

// ---- scratch (static device globals) ----
__device__ __align__(16) __half g_h[(size_t)NN * DD];           // h' (fp16, dinv-prescaled)
__device__ __align__(16) __nv_bfloat16 g_xh[(size_t)NN * DD];
__device__ __align__(16) __nv_bfloat16 g_xl[(size_t)NN * DD];
__device__ __align__(16) __nv_bfloat16 g_w1h[DD * DD], g_w1l[DD * DD];
__device__ __align__(16) __nv_bfloat16 g_w2h[DD * DD], g_w2l[DD * DD];
__device__ int   g_deg[NN];
__device__ float g_dinv[NN];
__device__ int   g_rowptr[NN + 1];
__device__ int   g_cursor[NN];
__device__ int   g_csr_src[NE];
__device__ int   g_blocksums[NB_SCAN];

__device__ __forceinline__ uint32_t smem_u32(const void* p) {
    uint32_t a;
    asm("{ .reg .u64 t; cvta.to.shared.u64 t, %1; cvt.u32.u64 %0, t; }" : "=r"(a) : "l"(p));
    return a;
}
__device__ __forceinline__ void ldsm4(uint32_t* r, uint32_t addr) {
    asm volatile("ldmatrix.sync.aligned.m8n8.x4.shared.b16 {%0,%1,%2,%3}, [%4];"
        : "=r"(r[0]), "=r"(r[1]), "=r"(r[2]), "=r"(r[3]) : "r"(addr));
}
__device__ __forceinline__ void ldsm4t(uint32_t* r, uint32_t addr) {
    asm volatile("ldmatrix.sync.aligned.m8n8.x4.trans.shared.b16 {%0,%1,%2,%3}, [%4];"
        : "=r"(r[0]), "=r"(r[1]), "=r"(r[2]), "=r"(r[3]) : "r"(addr));
}
__device__ __forceinline__ void mma16816(float* c, const uint32_t* a, uint32_t b0, uint32_t b1) {
    asm volatile("mma.sync.aligned.m16n8k16.row.col.f32.bf16.bf16.f32 "
        "{%0,%1,%2,%3}, {%4,%5,%6,%7}, {%8,%9}, {%0,%1,%2,%3};"
        : "+f"(c[0]), "+f"(c[1]), "+f"(c[2]), "+f"(c[3])
        : "r"(a[0]), "r"(a[1]), "r"(a[2]), "r"(a[3]), "r"(b0), "r"(b1));
}
__device__ __forceinline__ float4 h4_to_f4(uint2 v) {
    __half2 p0 = *(__half2*)&v.x, p1 = *(__half2*)&v.y;
    float2 f0 = __half22float2(p0), f1 = __half22float2(p1);
    return make_float4(f0.x, f0.y, f1.x, f1.y);
}

// ---------------- degree / norm / CSR build ----------------
__global__ void count_deg_kernel(const int* __restrict__ dst) {
    int e = blockIdx.x * blockDim.x + threadIdx.x;
    if (e < NE) { int d = __ldg(dst + e); if ((unsigned)d < NN) atomicAdd(&g_deg[d], 1); }
}
__global__ void dinv_kernel() {
    int i = blockIdx.x * blockDim.x + threadIdx.x;
    if (i < NN) g_dinv[i] = rsqrtf((float)(g_deg[i] + 1));
}
// block scan (shfl-based)
__global__ void scan_block_kernel() {
    __shared__ int wsum[32];
    int i = blockIdx.x * SCAN_B + threadIdx.x;
    int lane = threadIdx.x & 31, wid = threadIdx.x >> 5;
    int v = (i < NN) ? g_deg[i] : 0;
    int x = v;
#pragma unroll
    for (int o = 1; o < 32; o <<= 1) {
        int t = __shfl_up_sync(0xFFFFFFFFu, x, o);
        if (lane >= o) x += t;
    }
    if (lane == 31) wsum[wid] = x;
    __syncthreads();
    if (wid == 0) {
        int s = wsum[lane];
        int y = s;
#pragma unroll
        for (int o = 1; o < 32; o <<= 1) {
            int t = __shfl_up_sync(0xFFFFFFFFu, y, o);
            if (lane >= o) y += t;
        }
        wsum[lane] = y - s;
    }
    __syncthreads();
    int incl = x + wsum[wid];
    if (i < NN) g_rowptr[i] = incl - v;
    if (threadIdx.x == SCAN_B - 1) g_blocksums[blockIdx.x] = incl;
}
__global__ void scan_add_kernel() {
    __shared__ int red[128];
    int t = threadIdx.x, bid = blockIdx.x;
    int v = 0;
    if (t < 128) {
        for (int k = t; k < bid; k += 128) v += g_blocksums[k];
        red[t] = v;
    }
    __syncthreads();
#pragma unroll
    for (int o = 64; o > 0; o >>= 1) {
        if (t < o) red[t] += red[t + o];
        __syncthreads();
    }
    int base = red[0];
    int i = bid * SCAN_B + t;
    if (i < NN) {
        int r = g_rowptr[i] + base;
        g_rowptr[i] = r;
        g_cursor[i] = r;
    }
    if (i == 0) g_rowptr[NN] = NE;
}
__global__ void bin_edges_kernel(const int* __restrict__ ei) {
    int e = blockIdx.x * blockDim.x + threadIdx.x;
    if (e >= NE) return;
    int s = __ldg(ei + e), d = __ldg(ei + NE + e);
    if ((unsigned)s >= NN || (unsigned)d >= NN) return;
    g_csr_src[atomicAdd(&g_cursor[d], 1)] = s;
}

// ---------------- weight conversion (both layers, one launch) ----------------
__global__ void convert_w2x(const float* __restrict__ W1, const float* __restrict__ W2) {
    int idx = blockIdx.x * blockDim.x + threadIdx.x;
    if (idx >= 2 * DD * DD) return;
    int which = idx >= DD * DD;
    int i = idx - which * DD * DD;
    float v = which ? W2[i] : W1[i];
    __nv_bfloat16 h = __float2bfloat16(v);
    __nv_bfloat16 l = __float2bfloat16(v - __bfloat162float(h));
    if (which) { g_w2h[i] = h; g_w2l[i] = l; }
    else       { g_w1h[i] = h; g_w1l[i] = l; }
}

// ---------------- mma.sync bf16-split GEMM: out[r,:] = fp16((x @ W) * dinv[r]) ----------------
template <int SPLIT>
__global__ void __launch_bounds__(256, 2)
mma_gemm(const float* __restrict__ Xf,
         const __nv_bfloat16* __restrict__ Xh, const __nv_bfloat16* __restrict__ Xl,
         const __nv_bfloat16* __restrict__ Wh, const __nv_bfloat16* __restrict__ Wl,
         __half* __restrict__ out) {
    extern __shared__ __align__(16) char smem[];
    const int tid = threadIdx.x, w = tid >> 5, lane = tid & 31;

    {
        int r = tid >> 1, half = tid & 1;
        int gr = blockIdx.x * TM + r;
        if (SPLIT) {
            uint2* dH = (uint2*)(smem + AH_OFF + r * PADB + half * 96);
            uint2* dL = (uint2*)(smem + AL_OFF + r * PADB + half * 96);
            if (gr < NN) {
                const float4* s = (const float4*)(Xf + (size_t)gr * DD) + half * 12;
#pragma unroll
                for (int i = 0; i < 12; i++) {
                    float4 v = s[i];
                    __nv_bfloat162 h0 = __floats2bfloat162_rn(v.x, v.y);
                    __nv_bfloat162 h1 = __floats2bfloat162_rn(v.z, v.w);
                    __nv_bfloat162 l0 = __floats2bfloat162_rn(v.x - __bfloat162float(h0.x),
                                                              v.y - __bfloat162float(h0.y));
                    __nv_bfloat162 l1 = __floats2bfloat162_rn(v.z - __bfloat162float(h1.x),
                                                              v.w - __bfloat162float(h1.y));
                    dH[i] = make_uint2(*(uint32_t*)&h0, *(uint32_t*)&h1);
                    dL[i] = make_uint2(*(uint32_t*)&l0, *(uint32_t*)&l1);
                }
            } else {
                uint2 z = make_uint2(0, 0);
#pragma unroll
                for (int i = 0; i < 12; i++) { dH[i] = z; dL[i] = z; }
            }
        } else {
            uint4* dH = (uint4*)(smem + AH_OFF + r * PADB + half * 96);
            uint4* dL = (uint4*)(smem + AL_OFF + r * PADB + half * 96);
            if (gr < NN) {
                const uint4* sH = (const uint4*)(Xh + (size_t)gr * DD) + half * 6;
                const uint4* sL = (const uint4*)(Xl + (size_t)gr * DD) + half * 6;
#pragma unroll
                for (int i = 0; i < 6; i++) { dH[i] = sH[i]; dL[i] = sL[i]; }
            } else {
                uint4 z = make_uint4(0, 0, 0, 0);
#pragma unroll
                for (int i = 0; i < 6; i++) { dH[i] = z; dL[i] = z; }
            }
        }
    }
    if (tid < DD) {
        uint4* d = (uint4*)(smem + WH_OFF + tid * PADB);
        const uint4* s = (const uint4*)(Wh + (size_t)tid * DD);
#pragma unroll
        for (int i = 0; i < 12; i++) d[i] = s[i];
    } else if (tid >= 128 && tid < 128 + DD) {
        int r = tid - 128;
        uint4* d = (uint4*)(smem + WL_OFF + r * PADB);
        const uint4* s = (const uint4*)(Wl + (size_t)r * DD);
#pragma unroll
        for (int i = 0; i < 12; i++) d[i] = s[i];
    }
    __syncthreads();

    const uint32_t sb = smem_u32(smem);
    float acc[12][4];
#pragma unroll
    for (int t = 0; t < 12; t++)
#pragma unroll
        for (int q = 0; q < 4; q++) acc[t][q] = 0.f;

    const uint32_t aH = sb + AH_OFF + (w * 16 + (lane & 15)) * PADB + (lane >> 4) * 16;
    const uint32_t aL = sb + AL_OFF + (w * 16 + (lane & 15)) * PADB + (lane >> 4) * 16;
    const uint32_t bH = sb + WH_OFF + (lane & 15) * PADB + (lane >> 4) * 16;
    const uint32_t bL = sb + WL_OFF + (lane & 15) * PADB + (lane >> 4) * 16;

#pragma unroll
    for (int ks = 0; ks < 6; ks++) {
        uint32_t ah[4], al[4];
        ldsm4(ah, aH + ks * 32);
        ldsm4(al, aL + ks * 32);
#pragma unroll
        for (int nb = 0; nb < 6; nb++) {
            uint32_t bh[4], bl[4];
            ldsm4t(bh, bH + ks * 16 * PADB + nb * 32);
            ldsm4t(bl, bL + ks * 16 * PADB + nb * 32);
            mma16816(acc[2 * nb],     ah, bh[0], bh[1]);
            mma16816(acc[2 * nb],     ah, bl[0], bl[1]);
            mma16816(acc[2 * nb],     al, bh[0], bh[1]);
            mma16816(acc[2 * nb + 1], ah, bh[2], bh[3]);
            mma16816(acc[2 * nb + 1], ah, bl[2], bl[3]);
            mma16816(acc[2 * nb + 1], al, bh[2], bh[3]);
        }
    }

    int r0 = blockIdx.x * TM + w * 16 + (lane >> 2);
    int c0 = (lane & 3) * 2;
    float d0 = (r0 < NN) ? g_dinv[r0] : 0.f;
    float d1 = (r0 + 8 < NN) ? g_dinv[r0 + 8] : 0.f;
#pragma unroll
    for (int nt = 0; nt < 12; nt++) {
        int col = nt * 8 + c0;
        if (r0 < NN)
            ((__half2*)(out + (size_t)r0 * DD))[col >> 1] =
                __floats2half2_rn(acc[nt][0] * d0, acc[nt][1] * d0);
        if (r0 + 8 < NN)
            ((__half2*)(out + (size_t)(r0 + 8) * DD))[col >> 1] =
                __floats2half2_rn(acc[nt][2] * d1, acc[nt][3] * d1);
    }
}

// ---------------- pull aggregation (fp16 rows, fp32 accumulation) ----------------
template <int BN>
__global__ void __launch_bounds__(256)
gather_nodes(const __half* __restrict__ h, const float* __restrict__ bias,
             const float* __restrict__ gamma, const float* __restrict__ beta,
             const float* __restrict__ mean,  const float* __restrict__ var,
             float* __restrict__ outf) {
    int n    = (blockIdx.x * blockDim.x + threadIdx.x) >> 5;
    int lane = threadIdx.x & 31;
    if (n >= NN || lane >= D4) return;

    float4 acc = h4_to_f4(((const uint2*)(h + (size_t)n * DD))[lane]);

    int off = g_rowptr[n], end = g_rowptr[n + 1];
    for (; off + 7 < end; off += 8) {
        int s[8];
#pragma unroll
        for (int k = 0; k < 8; k++) s[k] = g_csr_src[off + k];
        uint2 v[8];
#pragma unroll
        for (int k = 0; k < 8; k++) v[k] = ((const uint2*)(h + (size_t)s[k] * DD))[lane];
#pragma unroll
        for (int k = 0; k < 8; k++) {
            float4 f = h4_to_f4(v[k]);
            acc.x += f.x; acc.y += f.y; acc.z += f.z; acc.w += f.w;
        }
    }
    for (; off + 3 < end; off += 4) {
        uint2 v0 = ((const uint2*)(h + (size_t)g_csr_src[off]     * DD))[lane];
        uint2 v1 = ((const uint2*)(h + (size_t)g_csr_src[off + 1] * DD))[lane];
        uint2 v2 = ((const uint2*)(h + (size_t)g_csr_src[off + 2] * DD))[lane];
        uint2 v3 = ((const uint2*)(h + (size_t)g_csr_src[off + 3] * DD))[lane];
        float4 f0 = h4_to_f4(v0), f1 = h4_to_f4(v1), f2 = h4_to_f4(v2), f3 = h4_to_f4(v3);
        acc.x += f0.x + f1.x + f2.x + f3.x;
        acc.y += f0.y + f1.y + f2.y + f3.y;
        acc.z += f0.z + f1.z + f2.z + f3.z;
        acc.w += f0.w + f1.w + f2.w + f3.w;
    }
    for (; off < end; off++) {
        float4 f = h4_to_f4(((const uint2*)(h + (size_t)g_csr_src[off] * DD))[lane]);
        acc.x += f.x; acc.y += f.y; acc.z += f.z; acc.w += f.w;
    }

    float dn = g_dinv[n];
    float4 bb = ((const float4*)bias)[lane];
    acc.x = fmaf(acc.x, dn, bb.x);
    acc.y = fmaf(acc.y, dn, bb.y);
    acc.z = fmaf(acc.z, dn, bb.z);
    acc.w = fmaf(acc.w, dn, bb.w);

    if (BN) {
        float4 G = ((const float4*)gamma)[lane];
        float4 B = ((const float4*)beta)[lane];
        float4 M = ((const float4*)mean)[lane];
        float4 V = ((const float4*)var)[lane];
        acc.x = acc.x >= 0.f ? acc.x : 0.05f * acc.x;
        acc.y = acc.y >= 0.f ? acc.y : 0.05f * acc.y;
        acc.z = acc.z >= 0.f ? acc.z : 0.05f * acc.z;
        acc.w = acc.w >= 0.f ? acc.w : 0.05f * acc.w;
        acc.x = fmaf((acc.x - M.x) * rsqrtf(V.x + 1e-5f), G.x, B.x);
        acc.y = fmaf((acc.y - M.y) * rsqrtf(V.y + 1e-5f), G.y, B.y);
        acc.z = fmaf((acc.z - M.z) * rsqrtf(V.z + 1e-5f), G.z, B.z);
        acc.w = fmaf((acc.w - M.w) * rsqrtf(V.w + 1e-5f), G.w, B.w);
        __nv_bfloat162 h0 = __floats2bfloat162_rn(acc.x, acc.y);
        __nv_bfloat162 h1 = __floats2bfloat162_rn(acc.z, acc.w);
        __nv_bfloat162 l0 = __floats2bfloat162_rn(acc.x - __bfloat162float(h0.x), acc.y - __bfloat162float(h0.y));
        __nv_bfloat162 l1 = __floats2bfloat162_rn(acc.z - __bfloat162float(h1.x), acc.w - __bfloat162float(h1.y));
        ((uint2*)g_xh)[n * D4 + lane] = make_uint2(*(uint32_t*)&h0, *(uint32_t*)&h1);
        ((uint2*)g_xl)[n * D4 + lane] = make_uint2(*(uint32_t*)&l0, *(uint32_t*)&l1);
    } else {
        ((float4*)(outf + (size_t)n * DD))[lane] = acc;
    }
}

// ---------------- launcher ----------------
extern "C" void kernel_launch(void* const* d_in, const int* in_sizes, int n_in,
                              void* d_out, int out_size) {
    const float* X     = (const float*)d_in[0];
    const int*   ei    = (const int*)d_in[1];
    const float* W1    = (const float*)d_in[2];
    const float* b1    = (const float*)d_in[3];
    const float* W2    = (const float*)d_in[4];
    const float* b2    = (const float*)d_in[5];
    const float* gamma = (const float*)d_in[6];
    const float* beta  = (const float*)d_in[7];
    const float* mean  = (const float*)d_in[8];
    const float* var   = (const float*)d_in[9];
    float* out = (float*)d_out;

    void* p;
    cudaGetSymbolAddress(&p, g_h);   __half* h = (__half*)p;
    cudaGetSymbolAddress(&p, g_xh);  __nv_bfloat16* xh = (__nv_bfloat16*)p;
    cudaGetSymbolAddress(&p, g_xl);  __nv_bfloat16* xl = (__nv_bfloat16*)p;
    cudaGetSymbolAddress(&p, g_w1h); __nv_bfloat16* w1h = (__nv_bfloat16*)p;
    cudaGetSymbolAddress(&p, g_w1l); __nv_bfloat16* w1l = (__nv_bfloat16*)p;
    cudaGetSymbolAddress(&p, g_w2h); __nv_bfloat16* w2h = (__nv_bfloat16*)p;
    cudaGetSymbolAddress(&p, g_w2l); __nv_bfloat16* w2l = (__nv_bfloat16*)p;
    void* degp; cudaGetSymbolAddress(&degp, g_deg);

    cudaFuncSetAttribute(mma_gemm<0>, cudaFuncAttributeMaxDynamicSharedMemorySize, SMEM_TOTAL);
    cudaFuncSetAttribute(mma_gemm<1>, cudaFuncAttributeMaxDynamicSharedMemorySize, SMEM_TOTAL);

    static cudaStream_t s2 = nullptr;
    static cudaEvent_t evA = nullptr, evD = nullptr, evG = nullptr;
    if (!s2) {
        cudaStreamCreate(&s2);
        cudaEventCreateWithFlags(&evA, cudaEventDisableTiming);
        cudaEventCreateWithFlags(&evD, cudaEventDisableTiming);
        cudaEventCreateWithFlags(&evG, cudaEventDisableTiming);
    }

    const int TPB = 256;
    int nodeBlocks = (NN + TPB - 1) / TPB;
    int edgeBlocks = (NE + TPB - 1) / TPB;
    int wBlocks    = (2 * DD * DD + TPB - 1) / TPB;
    int gathBlocks = (NN + 7) / 8;

    // ---- stream 0: degree -> dinv (gates GEMM1) -> scan -> add -> bin ----
    cudaEventRecord(evA, 0);
    cudaMemsetAsync(degp, 0, NN * sizeof(int), 0);
    count_deg_kernel<<<edgeBlocks, TPB>>>(ei + NE);
    dinv_kernel<<<nodeBlocks, TPB>>>();
    cudaEventRecord(evD, 0);
    scan_block_kernel<<<NB_SCAN, SCAN_B>>>();
    scan_add_kernel<<<NB_SCAN, SCAN_B>>>();
    bin_edges_kernel<<<edgeBlocks, TPB>>>(ei);

    // ---- stream s2: weight conversion + layer-1 GEMM (overlaps scan/bin) ----
    cudaStreamWaitEvent(s2, evA, 0);
    convert_w2x<<<wBlocks, TPB, 0, s2>>>(W1, W2);
    cudaStreamWaitEvent(s2, evD, 0);
    mma_gemm<1><<<NT, 256, SMEM_TOTAL, s2>>>(X, nullptr, nullptr, w1h, w1l, h);
    cudaEventRecord(evG, s2);

    // ---- join: gather1 needs CSR (stream 0) + h' (s2) ----
    cudaStreamWaitEvent(0, evG, 0);
    gather_nodes<1><<<gathBlocks, TPB>>>(h, b1, gamma, beta, mean, var, nullptr);

    // layer 2 (serial)
    mma_gemm<0><<<NT, 256, SMEM_TOTAL>>>(nullptr, xh, xl, w2h, w2l, h);
    gather_nodes<0><<<gathBlocks, TPB>>>(h, b2, gamma, beta, mean, var, out);
}